// round 14
// baseline (speedup 1.0000x reference)
#include <cuda_runtime.h>
#include <cuda_fp16.h>
#include <math.h>
#include <stdint.h>

#define BB 8
#define CC 128
#define EE 8
#define NG 4
#define PIX 9216
#define XROWS 10240     // x plane rows: 128 lead pad + pp + slack
#define NT2 38          // M-tiles of 256 padded pixels (conv and pw)
#define UROWS 9728      // u plane rows = 38*256 (fully written by conv)

// ---------------- device globals ----------------
__device__ float g_xgap[BB][CC];
__device__ float g_wt[NG][BB][EE];
__device__ int   g_sel[NG][BB][2];
__device__ int   g_mask[EE][BB];
__device__ float g_beff[NG][BB][CC];
__device__ uint32_t g_xt[(size_t)BB*4*XROWS*16];      // fp16 x, [b][chunk][row][32ci halves]
__device__ uint32_t g_wtb[(size_t)EE*9*4*CC*16];      // fp16 conv W, [e,tap,chunk][co][32ci halves]
__device__ uint32_t g_bp[(size_t)NG*BB*2*CC*64];      // fp16 gate-scaled pw W, [g,b,slot][co][128ci halves]
__device__ uint32_t g_ub[(size_t)EE*BB*UROWS*64];     // fp16 squashed u, [pair][row][128ci halves]

// ---------------- helpers ----------------
__device__ __forceinline__ uint32_t f2h2(float lo, float hi) {
    uint32_t r;
    asm("cvt.rn.f16x2.f32 %0, %1, %2;" : "=r"(r) : "f"(hi), "f"(lo));
    return r;
}
__device__ __forceinline__ uint32_t smem_u32(const void* p) {
    uint32_t a;
    asm("{ .reg .u64 t; cvta.to.shared.u64 t, %1; cvt.u32.u64 %0, t; }" : "=r"(a) : "l"(p));
    return a;
}
__device__ __forceinline__ void cpa16(uint32_t dst, const void* src) {
    asm volatile("cp.async.cg.shared.global [%0], [%1], 16;" :: "r"(dst), "l"(src) : "memory");
}
__device__ __forceinline__ void cpa_commit() {
    asm volatile("cp.async.commit_group;" ::: "memory");
}
__device__ __forceinline__ void cpa_wait1() {
    asm volatile("cp.async.wait_group 1;" ::: "memory");
}
__device__ __forceinline__ void cpa_wait0() {
    asm volatile("cp.async.wait_group 0;" ::: "memory");
}
__device__ __forceinline__ void mma16(float* c, const uint32_t* a, uint32_t b0, uint32_t b1) {
    asm volatile(
        "mma.sync.aligned.m16n8k16.row.col.f32.f16.f16.f32 "
        "{%0,%1,%2,%3},{%4,%5,%6,%7},{%8,%9},{%0,%1,%2,%3};"
        : "+f"(c[0]), "+f"(c[1]), "+f"(c[2]), "+f"(c[3])
        : "r"(a[0]), "r"(a[1]), "r"(a[2]), "r"(a[3]), "r"(b0), "r"(b1));
}
__device__ __forceinline__ void ldsm4(uint32_t* r, uint32_t addr) {
    asm volatile("ldmatrix.sync.aligned.m8n8.x4.shared.b16 {%0,%1,%2,%3}, [%4];"
                 : "=r"(r[0]), "=r"(r[1]), "=r"(r[2]), "=r"(r[3]) : "r"(addr));
}

// ---------------- K0: fused preps: packx (1152 blocks) + packw (576) + gap (1024) ----
__global__ void k_prep(const float* __restrict__ x, const float* __restrict__ Wc) {
    int bx = blockIdx.x;
    int t = threadIdx.x;
    if (bx < 1152) {
        // ---- packx: padded pixel-major fp16 planes ----
        int b = bx / 144, p0 = (bx % 144) * 64;
        __shared__ float sx[128][65];
        for (int i = t; i < 8192; i += 256) {
            int ci = i >> 6, p = i & 63;
            sx[ci][p] = x[((size_t)b * CC + ci) * PIX + p0 + p];
        }
        __syncthreads();
        for (int i = t; i < 1024; i += 256) {
            int p = i >> 4, c = (i >> 2) & 3, q = i & 3;
            int dp = p0 + p, h = dp / 96, w = dp % 96;
            int pp = (h + 1) * 98 + (w + 1) + 128;
            int ci0 = c * 32 + q * 8;
            uint4 v;
            v.x = f2h2(sx[ci0 + 0][p], sx[ci0 + 1][p]);
            v.y = f2h2(sx[ci0 + 2][p], sx[ci0 + 3][p]);
            v.z = f2h2(sx[ci0 + 4][p], sx[ci0 + 5][p]);
            v.w = f2h2(sx[ci0 + 6][p], sx[ci0 + 7][p]);
            ((uint4*)g_xt)[((size_t)(b * 4 + c) * XROWS + pp) * 4 + q] = v;
        }
    } else if (bx < 1728) {
        // ---- packw: conv weights [e,tap,chunk][co][32ci halves] ----
        int idx = (bx - 1152) * 256 + t;
        int q = idx & 3, co = (idx >> 2) & 127, c = (idx >> 9) & 3;
        int et = idx >> 11, tap = et % 9, e = et / 9;
        const float* s = Wc + (((size_t)(e * CC + co) * CC + c * 32 + q * 8) * 9 + tap);
        uint4 v;
        v.x = f2h2(s[0],  s[9]);
        v.y = f2h2(s[18], s[27]);
        v.z = f2h2(s[36], s[45]);
        v.w = f2h2(s[54], s[63]);
        ((uint4*)g_wtb)[idx] = v;
    } else {
        // ---- gap: global average pool ----
        int bc = bx - 1728;
        const float* p = x + (size_t)bc * PIX;
        float s = 0.f;
        for (int i = t; i < PIX; i += 256) s += p[i];
        __shared__ float red[8];
        #pragma unroll
        for (int o = 16; o; o >>= 1) s += __shfl_down_sync(0xffffffffu, s, o);
        if ((t & 31) == 0) red[t >> 5] = s;
        __syncthreads();
        if (t < 8) {
            s = red[t];
            #pragma unroll
            for (int o = 4; o; o >>= 1) s += __shfl_down_sync(0xffu, s, o);
            if (t == 0) g_xgap[bc >> 7][bc & 127] = s * (1.0f / PIX);
        }
    }
}

// ---------------- K1: gating, top-2, combine weights, loss ----------------
__global__ void k_gate(const float* __restrict__ G, const float* __restrict__ bp,
                       float* __restrict__ dout) {
    __shared__ float probs[BB][EE];
    __shared__ float losses[NG];
    int t = threadIdx.x;
    if (t < EE * BB) g_mask[t / BB][t % BB] = 0;
    __syncthreads();
    for (int g = 0; g < NG; g++) {
        if (t < BB * EE) {
            int b = t >> 3, e = t & 7;
            float s = 0.f;
            for (int c = 0; c < CC; c++) s += g_xgap[b][c] * G[(g * CC + c) * EE + e];
            probs[b][e] = s;
        }
        __syncthreads();
        if (t < BB) {
            int b = t;
            float mx = probs[b][0];
            #pragma unroll
            for (int e = 1; e < EE; e++) mx = fmaxf(mx, probs[b][e]);
            float pr[EE]; float sum = 0.f;
            #pragma unroll
            for (int e = 0; e < EE; e++) { pr[e] = expf(probs[b][e] - mx); sum += pr[e]; }
            float inv = 1.f / sum;
            #pragma unroll
            for (int e = 0; e < EE; e++) { pr[e] *= inv; probs[b][e] = pr[e]; }
            int i0 = 0;
            #pragma unroll
            for (int e = 1; e < EE; e++) if (pr[e] > pr[i0]) i0 = e;
            int i1 = (i0 == 0) ? 1 : 0;
            #pragma unroll
            for (int e = 0; e < EE; e++) if (e != i0 && pr[e] > pr[i1]) i1 = e;
            float e1 = expf(pr[i1] - pr[i0]);
            float tw0 = 1.f / (1.f + e1), tw1 = e1 / (1.f + e1);
            #pragma unroll
            for (int e = 0; e < EE; e++) g_wt[g][b][e] = 0.f;
            g_wt[g][b][i0] = tw0; g_wt[g][b][i1] = tw1;
            g_sel[g][b][0] = i0; g_sel[g][b][1] = i1;
            g_mask[i0][b] = 1; g_mask[i1][b] = 1;
        }
        __syncthreads();
        if (t == 0) {
            float v[EE]; float mean = 0.f;
            #pragma unroll
            for (int e = 0; e < EE; e++) {
                float s = 0.f;
                for (int b = 0; b < BB; b++) s += probs[b][e];
                v[e] = s; mean += s;
            }
            mean *= (1.0f / EE);
            float var = 0.f;
            #pragma unroll
            for (int e = 0; e < EE; e++) { float d = v[e] - mean; var += d * d; }
            var *= (1.0f / (EE - 1));
            losses[g] = var / (mean * mean + 1e-10f);
        }
        __syncthreads();
    }
    if (t < CC) {
        for (int g = 0; g < NG; g++)
            for (int b = 0; b < BB; b++) {
                float s = 0.f;
                #pragma unroll
                for (int e = 0; e < EE; e++) s += g_wt[g][b][e] * bp[e * CC + t];
                g_beff[g][b][t] = s;
            }
    }
    if (t == 0)
        dout[(size_t)NG * BB * CC * PIX] =
            0.25f * (losses[0] + losses[1] + losses[2] + losses[3]);
}

// ---------------- pack gate-scaled pw weights: [g,b,slot][co][128ci halves] ------------
__global__ void k_packbp(const float* __restrict__ Wp) {
    int idx = blockIdx.x * 256 + threadIdx.x;
    int q = idx & 15, co = (idx >> 4) & 127, slot = (idx >> 11) & 1;
    int b = (idx >> 12) & 7, g = idx >> 15;
    int e = g_sel[g][b][slot];
    float wv = g_wt[g][b][e];
    const float* s = Wp + (size_t)e * CC * CC + (size_t)co * CC + q * 8;
    uint4 v;
    v.x = f2h2(s[0] * wv, s[1] * wv);
    v.y = f2h2(s[2] * wv, s[3] * wv);
    v.z = f2h2(s[4] * wv, s[5] * wv);
    v.w = f2h2(s[6] * wv, s[7] * wv);
    ((uint4*)g_bp)[idx] = v;
}

// ---------------- conv: fp16 m16n8k16, M=256 tile, 256 threads, warp tile 64x64 ------
// 8 warps: wm = wid&3 (64 rows), wn = wid>>2 (64 cols). ldmatrix fragment loads.
#define CV_XS0 0
#define CV_XS1 9080              // 454*20
#define CV_WSA 18160             // 128*20 each
#define CV_WSB 20720
#define CV_W2A 23280
#define CV_W2B 25840
#define CV_BIAS 28400
#define CV_SS   28528
#define CV_SMEMB ((28528 + 256) * 4)   // 115,136 B

__global__ void __launch_bounds__(256) k_conv_mma(const float* __restrict__ bc) {
    int e = blockIdx.z, b = blockIdx.y;
    if (!g_mask[e][b]) return;
    extern __shared__ uint32_t S[];
    float* bias = (float*)(S + CV_BIAS);
    float* ssm  = (float*)(S + CV_SS);
    int t = threadIdx.x, lane = t & 31, wid = t >> 5;
    int wm = wid & 3, wn = wid >> 2;
    int gp = lane >> 2, tg = lane & 3;
    int q0 = blockIdx.x * 256;
    uint32_t sbase = smem_u32(S);
    ssm[t] = 0.f;
    if (t < 128) bias[t] = bc[e * CC + t];

    // ldmatrix per-lane address components
    int arow_l = ((lane >> 3) & 1) * 8 + (lane & 7);   // A: row within 16
    int acol_l = (lane >> 4) * 4;                      // A: word col (0 or 4)
    int bm = lane >> 3;
    int brow_l = (lane & 7) + ((bm >> 1) * 8);         // B: n within 16 (pair of n8)
    int bcol_l = (bm & 1) * 4;                         // B: word col (0 or 4)

    float acc[4][8][4];
    #pragma unroll
    for (int mt = 0; mt < 4; mt++)
        #pragma unroll
        for (int nt = 0; nt < 8; nt++)
            #pragma unroll
            for (int k = 0; k < 4; k++) acc[mt][nt][k] = 0.f;
    const int drow[9] = {0, 1, 2, 98, 99, 100, 196, 197, 198};

    // prologue: chunk0 x tile + chunk0 tap0 weights
    {
        const uint4* xsrc = (const uint4*)g_xt + ((size_t)(b * 4 + 0) * XROWS + q0 + 29) * 4;
        for (int i = t; i < 1816; i += 256) {
            int r = i >> 2, q = i & 3;
            cpa16(sbase + (CV_XS0 + r * 20 + q * 4) * 4, xsrc + i);
        }
        const uint4* wsrc = (const uint4*)g_wtb + (size_t)((e * 9 + 0) * 4 + 0) * 512;
        for (int i = t; i < 512; i += 256) {
            int co = i >> 2, q = i & 3;
            cpa16(sbase + (CV_W2A + co * 20 + q * 4) * 4, wsrc + i);
        }
        cpa_commit();
    }

    for (int c = 0; c < 4; c++) {
        if (c < 3) {
            int cn = c + 1;
            uint32_t xoff = (cn & 1) ? CV_XS1 : CV_XS0;
            const uint4* xsrc = (const uint4*)g_xt + ((size_t)(b * 4 + cn) * XROWS + q0 + 29) * 4;
            for (int i = t; i < 1816; i += 256) {
                int r = i >> 2, q = i & 3;
                cpa16(sbase + (xoff + r * 20 + q * 4) * 4, xsrc + i);
            }
            uint32_t w2off = (cn & 1) ? CV_W2B : CV_W2A;
            const uint4* wsrc = (const uint4*)g_wtb + (size_t)((e * 9 + 0) * 4 + cn) * 512;
            for (int i = t; i < 512; i += 256) {
                int co = i >> 2, q = i & 3;
                cpa16(sbase + (w2off + co * 20 + q * 4) * 4, wsrc + i);
            }
            cpa_commit();
            cpa_wait1();
        } else {
            cpa_wait0();
        }
        __syncthreads();
        uint32_t xoffc = (c & 1) ? CV_XS1 : CV_XS0;

        for (int tap = 0; tap < 9; tap++) {
            uint32_t woff = (tap == 0)
                ? ((c & 1) ? CV_W2B : CV_W2A)
                : (((tap - 1) & 1) ? CV_WSB : CV_WSA);
            uint4 pf[2];
            bool hp = (tap < 8);
            if (hp) {
                const uint4* wsrc = (const uint4*)g_wtb + (size_t)((e * 9 + tap + 1) * 4 + c) * 512;
                pf[0] = wsrc[t];
                pf[1] = wsrc[t + 256];
            }
            int rb0 = wm * 64 + drow[tap];
            #pragma unroll
            for (int ks = 0; ks < 2; ks++) {
                uint32_t a[4][4], bb[4][4];
                #pragma unroll
                for (int mt = 0; mt < 4; mt++)
                    ldsm4(a[mt], sbase + (xoffc + (rb0 + mt * 16 + arow_l) * 20
                                          + ks * 8 + acol_l) * 4);
                #pragma unroll
                for (int np = 0; np < 4; np++)
                    ldsm4(bb[np], sbase + (woff + (wn * 64 + np * 16 + brow_l) * 20
                                           + ks * 8 + bcol_l) * 4);
                #pragma unroll
                for (int np = 0; np < 4; np++)
                    #pragma unroll
                    for (int mt = 0; mt < 4; mt++) {
                        mma16(acc[mt][2 * np],     a[mt], bb[np][0], bb[np][1]);
                        mma16(acc[mt][2 * np + 1], a[mt], bb[np][2], bb[np][3]);
                    }
            }
            if (hp) {
                uint32_t* wd = S + ((tap & 1) ? CV_WSB : CV_WSA);
                {
                    int co = t >> 2, q = t & 3;
                    *(uint4*)&wd[co * 20 + q * 4] = pf[0];
                    int i = t + 256;
                    co = i >> 2; q = i & 3;
                    *(uint4*)&wd[co * 20 + q * 4] = pf[1];
                }
            }
            __syncthreads();
        }
    }

    // epilogue: bias + relu + per-pixel squash + fp16 store
    float ssq[4][2];
    #pragma unroll
    for (int mt = 0; mt < 4; mt++) { ssq[mt][0] = 0.f; ssq[mt][1] = 0.f; }
    #pragma unroll
    for (int mt = 0; mt < 4; mt++)
        #pragma unroll
        for (int nt = 0; nt < 8; nt++)
            #pragma unroll
            for (int k = 0; k < 4; k++) {
                int col = wn * 64 + nt * 8 + 2 * tg + (k & 1);
                float v = fmaxf(acc[mt][nt][k] + bias[col], 0.f);
                acc[mt][nt][k] = v;
                ssq[mt][k >> 1] += v * v;
            }
    #pragma unroll
    for (int mt = 0; mt < 4; mt++)
        #pragma unroll
        for (int h = 0; h < 2; h++) {
            float s = ssq[mt][h];
            s += __shfl_xor_sync(0xffffffffu, s, 1);
            s += __shfl_xor_sync(0xffffffffu, s, 2);
            if (tg == 0) atomicAdd(&ssm[wm * 64 + mt * 16 + gp + 8 * h], s);
        }
    __syncthreads();
    uint32_t* up = g_ub + (size_t)(e * BB + b) * UROWS * 64;
    #pragma unroll
    for (int mt = 0; mt < 4; mt++)
        #pragma unroll
        for (int h = 0; h < 2; h++) {
            int r = wm * 64 + mt * 16 + gp + 8 * h;
            int q = q0 + r;
            float s = ssm[r];
            float sc = s / (1.f + s) * rsqrtf(s + 1e-8f);
            #pragma unroll
            for (int nt = 0; nt < 8; nt++) {
                up[(size_t)q * 64 + wn * 32 + nt * 4 + tg] =
                    f2h2(acc[mt][nt][h * 2] * sc, acc[mt][nt][h * 2 + 1] * sc);
            }
        }
}

// ---------------- pw: fp16 K-stacked GEMM, M=256 tile, 256 threads, ldmatrix ---------
#define PW_US0 0
#define PW_US1 5120              // 256*20 each
#define PW_WS0 10240             // 128*20 each
#define PW_WS1 12800
#define PW_BIAS 16896            // stage[128][132] floats reuses words 0..16895
#define PW_SMEMB ((16896 + 128) * 4)   // 68,096 B

__global__ void __launch_bounds__(256) k_pw_mma(float* __restrict__ out) {
    int g = blockIdx.z, b = blockIdx.y, q0 = blockIdx.x * 256;
    extern __shared__ uint32_t S[];
    float* bias = (float*)(S + PW_BIAS);
    int t = threadIdx.x, lane = t & 31, wid = t >> 5;
    int wm = wid & 3, wn = wid >> 2;
    int gp = lane >> 2, tg = lane & 3;
    uint32_t sbase = smem_u32(S);
    if (t < 128) bias[t] = g_beff[g][b][t];

    int arow_l = ((lane >> 3) & 1) * 8 + (lane & 7);
    int acol_l = (lane >> 4) * 4;
    int bm = lane >> 3;
    int brow_l = (lane & 7) + ((bm >> 1) * 8);
    int bcol_l = (bm & 1) * 4;

    float acc[4][8][4];
    #pragma unroll
    for (int mt = 0; mt < 4; mt++)
        #pragma unroll
        for (int nt = 0; nt < 8; nt++)
            #pragma unroll
            for (int k = 0; k < 4; k++) acc[mt][nt][k] = 0.f;

    {   // prologue: chunk0
        int e = g_sel[g][b][0];
        const uint4* usrc = (const uint4*)g_ub + ((size_t)(e * BB + b) * UROWS + q0) * 16;
        for (int i = t; i < 1024; i += 256) {
            int r = i >> 2, q = i & 3;
            cpa16(sbase + (PW_US0 + r * 20 + q * 4) * 4, usrc + (size_t)r * 16 + q);
        }
        const uint4* wsrc = (const uint4*)g_bp + (size_t)((g * BB + b) * 2 + 0) * 2048;
        for (int i = t; i < 512; i += 256) {
            int co = i >> 2, q = i & 3;
            cpa16(sbase + (PW_WS0 + co * 20 + q * 4) * 4, wsrc + co * 16 + q);
        }
        cpa_commit();
    }

    for (int kc = 0; kc < 8; kc++) {
        if (kc < 7) {
            int kn = kc + 1, slot = kn >> 2, c = kn & 3;
            int e = g_sel[g][b][slot];
            uint32_t uoff = (kn & 1) ? PW_US1 : PW_US0;
            uint32_t woff = (kn & 1) ? PW_WS1 : PW_WS0;
            const uint4* usrc = (const uint4*)g_ub + ((size_t)(e * BB + b) * UROWS + q0) * 16 + c * 4;
            for (int i = t; i < 1024; i += 256) {
                int r = i >> 2, q = i & 3;
                cpa16(sbase + (uoff + r * 20 + q * 4) * 4, usrc + (size_t)r * 16 + q);
            }
            const uint4* wsrc = (const uint4*)g_bp + (size_t)((g * BB + b) * 2 + slot) * 2048 + c * 4;
            for (int i = t; i < 512; i += 256) {
                int co = i >> 2, q = i & 3;
                cpa16(sbase + (woff + co * 20 + q * 4) * 4, wsrc + co * 16 + q);
            }
            cpa_commit();
            cpa_wait1();
        } else {
            cpa_wait0();
        }
        __syncthreads();
        uint32_t uoffc = (kc & 1) ? PW_US1 : PW_US0;
        uint32_t woffc = (kc & 1) ? PW_WS1 : PW_WS0;
        int rb0 = wm * 64;
        #pragma unroll
        for (int ks = 0; ks < 2; ks++) {
            uint32_t a[4][4], bb[4][4];
            #pragma unroll
            for (int mt = 0; mt < 4; mt++)
                ldsm4(a[mt], sbase + (uoffc + (rb0 + mt * 16 + arow_l) * 20
                                      + ks * 8 + acol_l) * 4);
            #pragma unroll
            for (int np = 0; np < 4; np++)
                ldsm4(bb[np], sbase + (woffc + (wn * 64 + np * 16 + brow_l) * 20
                                       + ks * 8 + bcol_l) * 4);
            #pragma unroll
            for (int np = 0; np < 4; np++)
                #pragma unroll
                for (int mt = 0; mt < 4; mt++) {
                    mma16(acc[mt][2 * np],     a[mt], bb[np][0], bb[np][1]);
                    mma16(acc[mt][2 * np + 1], a[mt], bb[np][2], bb[np][3]);
                }
        }
        __syncthreads();
    }

    // epilogue: two 128-pixel halves, transpose through smem -> coalesced stores
    float* stg = (float*)S;
    #pragma unroll
    for (int hh = 0; hh < 2; hh++) {
        __syncthreads();
        if ((wm >> 1) == hh) {
            #pragma unroll
            for (int mt = 0; mt < 4; mt++)
                #pragma unroll
                for (int k = 0; k < 4; k++) {
                    int r = wm * 64 + mt * 16 + gp + 8 * (k >> 1);
                    int rl = r - hh * 128;
                    #pragma unroll
                    for (int nt = 0; nt < 8; nt++) {
                        int col = wn * 64 + nt * 8 + 2 * tg + (k & 1);
                        stg[col * 132 + rl] = acc[mt][nt][k];
                    }
                }
        }
        __syncthreads();
        for (int i = t; i < 16384; i += 256) {
            int co = i >> 7, p = i & 127;
            int q = q0 + hh * 128 + p;
            int h = q / 98 - 1, w = q % 98 - 1;
            if ((unsigned)h < 96u && (unsigned)w < 96u)
                out[(((size_t)g * BB + b) * CC + co) * PIX + h * 96 + w] =
                    stg[co * 132 + p] + bias[co];
        }
    }
}

// ---------------- launch ----------------
extern "C" void kernel_launch(void* const* d_in, const int* in_sizes, int n_in,
                              void* d_out, int out_size) {
    const float* x  = (const float*)d_in[0];
    const float* G  = (const float*)d_in[1];
    const float* Wc = (const float*)d_in[2];
    const float* bc = (const float*)d_in[3];
    const float* Wp = (const float*)d_in[4];
    const float* bp = (const float*)d_in[5];
    float* out = (float*)d_out;

    cudaFuncSetAttribute(k_conv_mma, cudaFuncAttributeMaxDynamicSharedMemorySize, CV_SMEMB);
    cudaFuncSetAttribute(k_pw_mma,   cudaFuncAttributeMaxDynamicSharedMemorySize, PW_SMEMB);

    k_prep<<<2752, 256>>>(x, Wc);
    k_gate<<<1, 128>>>(G, bp, out);
    k_packbp<<<512, 256>>>(Wp);
    k_conv_mma<<<dim3(NT2, BB, EE), 256, CV_SMEMB>>>(bc);
    k_pw_mma<<<dim3(NT2, BB, NG), 256, PW_SMEMB>>>(out);
}

// round 15
// speedup vs baseline: 1.0790x; 1.0790x over previous
#include <cuda_runtime.h>
#include <cuda_fp16.h>
#include <math.h>
#include <stdint.h>

#define BB 8
#define CC 128
#define EE 8
#define NG 4
#define PIX 9216
#define XROWS 10240     // x plane rows: 128 lead pad + pp + slack
#define NTT 75          // pw M-tiles of 128 padded pixels
#define NT2 38          // conv M-tiles of 256 padded pixels
#define UROWS 9728      // u plane rows = 38*256 (fully written by conv)

// ---------------- device globals ----------------
__device__ float g_xgap[BB][CC];
__device__ float g_wt[NG][BB][EE];
__device__ int   g_sel[NG][BB][2];
__device__ int   g_mask[EE][BB];
__device__ float g_beff[NG][BB][CC];
__device__ uint32_t g_xt[(size_t)BB*4*XROWS*16];      // fp16 x, [b][chunk][row][32ci halves]
__device__ uint32_t g_wtb[(size_t)EE*9*4*CC*16];      // fp16 conv W, [e,tap,chunk][co][32ci halves]
__device__ uint32_t g_bp[(size_t)NG*BB*2*CC*64];      // fp16 gate-scaled pw W, [g,b,slot][co][128ci halves]
__device__ uint32_t g_ub[(size_t)EE*BB*UROWS*64];     // fp16 squashed u, [pair][row][128ci halves]

// ---------------- helpers ----------------
__device__ __forceinline__ uint32_t f2h2(float lo, float hi) {
    uint32_t r;
    asm("cvt.rn.f16x2.f32 %0, %1, %2;" : "=r"(r) : "f"(hi), "f"(lo));
    return r;
}
__device__ __forceinline__ uint32_t smem_u32(const void* p) {
    uint32_t a;
    asm("{ .reg .u64 t; cvta.to.shared.u64 t, %1; cvt.u32.u64 %0, t; }" : "=r"(a) : "l"(p));
    return a;
}
__device__ __forceinline__ void cpa16(uint32_t dst, const void* src) {
    asm volatile("cp.async.cg.shared.global [%0], [%1], 16;" :: "r"(dst), "l"(src) : "memory");
}
__device__ __forceinline__ void cpa_commit() {
    asm volatile("cp.async.commit_group;" ::: "memory");
}
__device__ __forceinline__ void cpa_wait1() {
    asm volatile("cp.async.wait_group 1;" ::: "memory");
}
__device__ __forceinline__ void cpa_wait0() {
    asm volatile("cp.async.wait_group 0;" ::: "memory");
}
__device__ __forceinline__ void mma16(float* c, const uint32_t* a, uint32_t b0, uint32_t b1) {
    asm volatile(
        "mma.sync.aligned.m16n8k16.row.col.f32.f16.f16.f32 "
        "{%0,%1,%2,%3},{%4,%5,%6,%7},{%8,%9},{%0,%1,%2,%3};"
        : "+f"(c[0]), "+f"(c[1]), "+f"(c[2]), "+f"(c[3])
        : "r"(a[0]), "r"(a[1]), "r"(a[2]), "r"(a[3]), "r"(b0), "r"(b1));
}
__device__ __forceinline__ void ldsm4(uint32_t* r, uint32_t addr) {
    asm volatile("ldmatrix.sync.aligned.m8n8.x4.shared.b16 {%0,%1,%2,%3}, [%4];"
                 : "=r"(r[0]), "=r"(r[1]), "=r"(r[2]), "=r"(r[3]) : "r"(addr));
}

// ---------------- K0: fused preps: packx (1152 blocks) + packw (576) + gap (1024) ----
__global__ void k_prep(const float* __restrict__ x, const float* __restrict__ Wc) {
    int bx = blockIdx.x;
    int t = threadIdx.x;
    if (bx < 1152) {
        int b = bx / 144, p0 = (bx % 144) * 64;
        __shared__ float sx[128][65];
        for (int i = t; i < 8192; i += 256) {
            int ci = i >> 6, p = i & 63;
            sx[ci][p] = x[((size_t)b * CC + ci) * PIX + p0 + p];
        }
        __syncthreads();
        for (int i = t; i < 1024; i += 256) {
            int p = i >> 4, c = (i >> 2) & 3, q = i & 3;
            int dp = p0 + p, h = dp / 96, w = dp % 96;
            int pp = (h + 1) * 98 + (w + 1) + 128;
            int ci0 = c * 32 + q * 8;
            uint4 v;
            v.x = f2h2(sx[ci0 + 0][p], sx[ci0 + 1][p]);
            v.y = f2h2(sx[ci0 + 2][p], sx[ci0 + 3][p]);
            v.z = f2h2(sx[ci0 + 4][p], sx[ci0 + 5][p]);
            v.w = f2h2(sx[ci0 + 6][p], sx[ci0 + 7][p]);
            ((uint4*)g_xt)[((size_t)(b * 4 + c) * XROWS + pp) * 4 + q] = v;
        }
    } else if (bx < 1728) {
        int idx = (bx - 1152) * 256 + t;
        int q = idx & 3, co = (idx >> 2) & 127, c = (idx >> 9) & 3;
        int et = idx >> 11, tap = et % 9, e = et / 9;
        const float* s = Wc + (((size_t)(e * CC + co) * CC + c * 32 + q * 8) * 9 + tap);
        uint4 v;
        v.x = f2h2(s[0],  s[9]);
        v.y = f2h2(s[18], s[27]);
        v.z = f2h2(s[36], s[45]);
        v.w = f2h2(s[54], s[63]);
        ((uint4*)g_wtb)[idx] = v;
    } else {
        int bc = bx - 1728;
        const float* p = x + (size_t)bc * PIX;
        float s = 0.f;
        for (int i = t; i < PIX; i += 256) s += p[i];
        __shared__ float red[8];
        #pragma unroll
        for (int o = 16; o; o >>= 1) s += __shfl_down_sync(0xffffffffu, s, o);
        if ((t & 31) == 0) red[t >> 5] = s;
        __syncthreads();
        if (t < 8) {
            s = red[t];
            #pragma unroll
            for (int o = 4; o; o >>= 1) s += __shfl_down_sync(0xffu, s, o);
            if (t == 0) g_xgap[bc >> 7][bc & 127] = s * (1.0f / PIX);
        }
    }
}

// ---------------- K1: gating, top-2, combine weights, loss ----------------
__global__ void k_gate(const float* __restrict__ G, const float* __restrict__ bp,
                       float* __restrict__ dout) {
    __shared__ float probs[BB][EE];
    __shared__ float losses[NG];
    int t = threadIdx.x;
    if (t < EE * BB) g_mask[t / BB][t % BB] = 0;
    __syncthreads();
    for (int g = 0; g < NG; g++) {
        if (t < BB * EE) {
            int b = t >> 3, e = t & 7;
            float s = 0.f;
            for (int c = 0; c < CC; c++) s += g_xgap[b][c] * G[(g * CC + c) * EE + e];
            probs[b][e] = s;
        }
        __syncthreads();
        if (t < BB) {
            int b = t;
            float mx = probs[b][0];
            #pragma unroll
            for (int e = 1; e < EE; e++) mx = fmaxf(mx, probs[b][e]);
            float pr[EE]; float sum = 0.f;
            #pragma unroll
            for (int e = 0; e < EE; e++) { pr[e] = expf(probs[b][e] - mx); sum += pr[e]; }
            float inv = 1.f / sum;
            #pragma unroll
            for (int e = 0; e < EE; e++) { pr[e] *= inv; probs[b][e] = pr[e]; }
            int i0 = 0;
            #pragma unroll
            for (int e = 1; e < EE; e++) if (pr[e] > pr[i0]) i0 = e;
            int i1 = (i0 == 0) ? 1 : 0;
            #pragma unroll
            for (int e = 0; e < EE; e++) if (e != i0 && pr[e] > pr[i1]) i1 = e;
            float e1 = expf(pr[i1] - pr[i0]);
            float tw0 = 1.f / (1.f + e1), tw1 = e1 / (1.f + e1);
            #pragma unroll
            for (int e = 0; e < EE; e++) g_wt[g][b][e] = 0.f;
            g_wt[g][b][i0] = tw0; g_wt[g][b][i1] = tw1;
            g_sel[g][b][0] = i0; g_sel[g][b][1] = i1;
            g_mask[i0][b] = 1; g_mask[i1][b] = 1;
        }
        __syncthreads();
        if (t == 0) {
            float v[EE]; float mean = 0.f;
            #pragma unroll
            for (int e = 0; e < EE; e++) {
                float s = 0.f;
                for (int b = 0; b < BB; b++) s += probs[b][e];
                v[e] = s; mean += s;
            }
            mean *= (1.0f / EE);
            float var = 0.f;
            #pragma unroll
            for (int e = 0; e < EE; e++) { float d = v[e] - mean; var += d * d; }
            var *= (1.0f / (EE - 1));
            losses[g] = var / (mean * mean + 1e-10f);
        }
        __syncthreads();
    }
    if (t < CC) {
        for (int g = 0; g < NG; g++)
            for (int b = 0; b < BB; b++) {
                float s = 0.f;
                #pragma unroll
                for (int e = 0; e < EE; e++) s += g_wt[g][b][e] * bp[e * CC + t];
                g_beff[g][b][t] = s;
            }
    }
    if (t == 0)
        dout[(size_t)NG * BB * CC * PIX] =
            0.25f * (losses[0] + losses[1] + losses[2] + losses[3]);
}

// ---------------- pack gate-scaled pw weights: [g,b,slot][co][128ci halves] ------------
__global__ void k_packbp(const float* __restrict__ Wp) {
    int idx = blockIdx.x * 256 + threadIdx.x;
    int q = idx & 15, co = (idx >> 4) & 127, slot = (idx >> 11) & 1;
    int b = (idx >> 12) & 7, g = idx >> 15;
    int e = g_sel[g][b][slot];
    float wv = g_wt[g][b][e];
    const float* s = Wp + (size_t)e * CC * CC + (size_t)co * CC + q * 8;
    uint4 v;
    v.x = f2h2(s[0] * wv, s[1] * wv);
    v.y = f2h2(s[2] * wv, s[3] * wv);
    v.z = f2h2(s[4] * wv, s[5] * wv);
    v.w = f2h2(s[6] * wv, s[7] * wv);
    ((uint4*)g_bp)[idx] = v;
}

// ---------------- conv: fp16 m16n8k16, M=256 tile, 512 threads, warp tile 64x32 ------
// 16 warps: wm = wid&3 (64 rows), wn = wid>>2 (32 cols). ldmatrix fragment loads.
#define CV_XS0 0
#define CV_XS1 9080              // 454*20
#define CV_WSA 18160             // 128*20 each
#define CV_WSB 20720
#define CV_W2A 23280
#define CV_W2B 25840
#define CV_BIAS 28400
#define CV_SS   28528
#define CV_SMEMB ((28528 + 256) * 4)   // 115,136 B

__global__ void __launch_bounds__(512) k_conv_mma(const float* __restrict__ bc) {
    int e = blockIdx.z, b = blockIdx.y;
    if (!g_mask[e][b]) return;
    extern __shared__ uint32_t S[];
    float* bias = (float*)(S + CV_BIAS);
    float* ssm  = (float*)(S + CV_SS);
    int t = threadIdx.x, lane = t & 31, wid = t >> 5;
    int wm = wid & 3, wn = wid >> 2;
    int gp = lane >> 2, tg = lane & 3;
    int q0 = blockIdx.x * 256;
    uint32_t sbase = smem_u32(S);
    if (t < 256) ssm[t] = 0.f;
    if (t < 128) bias[t] = bc[e * CC + t];

    // ldmatrix per-lane address components
    int arow_l = ((lane >> 3) & 1) * 8 + (lane & 7);   // A: row within 16
    int acol_l = (lane >> 4) * 4;                      // A: word col (0 or 4)
    int bm = lane >> 3;
    int brow_l = (lane & 7) + ((bm >> 1) * 8);         // B: n within 16 (pair of n8)
    int bcol_l = (bm & 1) * 4;                         // B: word col (0 or 4)

    float acc[4][4][4];
    #pragma unroll
    for (int mt = 0; mt < 4; mt++)
        #pragma unroll
        for (int nt = 0; nt < 4; nt++)
            #pragma unroll
            for (int k = 0; k < 4; k++) acc[mt][nt][k] = 0.f;
    const int drow[9] = {0, 1, 2, 98, 99, 100, 196, 197, 198};

    // prologue: chunk0 x tile + chunk0 tap0 weights
    {
        const uint4* xsrc = (const uint4*)g_xt + ((size_t)(b * 4 + 0) * XROWS + q0 + 29) * 4;
        for (int i = t; i < 1816; i += 512) {
            int r = i >> 2, q = i & 3;
            cpa16(sbase + (CV_XS0 + r * 20 + q * 4) * 4, xsrc + i);
        }
        const uint4* wsrc = (const uint4*)g_wtb + (size_t)((e * 9 + 0) * 4 + 0) * 512;
        {
            int co = t >> 2, q = t & 3;
            cpa16(sbase + (CV_W2A + co * 20 + q * 4) * 4, wsrc + t);
        }
        cpa_commit();
    }

    for (int c = 0; c < 4; c++) {
        if (c < 3) {
            int cn = c + 1;
            uint32_t xoff = (cn & 1) ? CV_XS1 : CV_XS0;
            const uint4* xsrc = (const uint4*)g_xt + ((size_t)(b * 4 + cn) * XROWS + q0 + 29) * 4;
            for (int i = t; i < 1816; i += 512) {
                int r = i >> 2, q = i & 3;
                cpa16(sbase + (xoff + r * 20 + q * 4) * 4, xsrc + i);
            }
            uint32_t w2off = (cn & 1) ? CV_W2B : CV_W2A;
            const uint4* wsrc = (const uint4*)g_wtb + (size_t)((e * 9 + 0) * 4 + cn) * 512;
            {
                int co = t >> 2, q = t & 3;
                cpa16(sbase + (w2off + co * 20 + q * 4) * 4, wsrc + t);
            }
            cpa_commit();
            cpa_wait1();
        } else {
            cpa_wait0();
        }
        __syncthreads();
        uint32_t xoffc = (c & 1) ? CV_XS1 : CV_XS0;

        for (int tap = 0; tap < 9; tap++) {
            uint32_t woff = (tap == 0)
                ? ((c & 1) ? CV_W2B : CV_W2A)
                : (((tap - 1) & 1) ? CV_WSB : CV_WSA);
            uint4 pf;
            bool hp = (tap < 8);
            if (hp) {
                const uint4* wsrc = (const uint4*)g_wtb + (size_t)((e * 9 + tap + 1) * 4 + c) * 512;
                pf = wsrc[t];
            }
            int rb0 = wm * 64 + drow[tap];
            #pragma unroll
            for (int ks = 0; ks < 2; ks++) {
                uint32_t a[4][4], bb[2][4];
                #pragma unroll
                for (int mt = 0; mt < 4; mt++)
                    ldsm4(a[mt], sbase + (xoffc + (rb0 + mt * 16 + arow_l) * 20
                                          + ks * 8 + acol_l) * 4);
                #pragma unroll
                for (int np = 0; np < 2; np++)
                    ldsm4(bb[np], sbase + (woff + (wn * 32 + np * 16 + brow_l) * 20
                                           + ks * 8 + bcol_l) * 4);
                #pragma unroll
                for (int np = 0; np < 2; np++)
                    #pragma unroll
                    for (int mt = 0; mt < 4; mt++) {
                        mma16(acc[mt][2 * np],     a[mt], bb[np][0], bb[np][1]);
                        mma16(acc[mt][2 * np + 1], a[mt], bb[np][2], bb[np][3]);
                    }
            }
            if (hp) {
                uint32_t* wd = S + ((tap & 1) ? CV_WSB : CV_WSA);
                int co = t >> 2, q = t & 3;
                *(uint4*)&wd[co * 20 + q * 4] = pf;
            }
            __syncthreads();
        }
    }

    // epilogue: bias + relu + per-pixel squash + fp16 store
    float ssq[4][2];
    #pragma unroll
    for (int mt = 0; mt < 4; mt++) { ssq[mt][0] = 0.f; ssq[mt][1] = 0.f; }
    #pragma unroll
    for (int mt = 0; mt < 4; mt++)
        #pragma unroll
        for (int nt = 0; nt < 4; nt++)
            #pragma unroll
            for (int k = 0; k < 4; k++) {
                int col = wn * 32 + nt * 8 + 2 * tg + (k & 1);
                float v = fmaxf(acc[mt][nt][k] + bias[col], 0.f);
                acc[mt][nt][k] = v;
                ssq[mt][k >> 1] += v * v;
            }
    #pragma unroll
    for (int mt = 0; mt < 4; mt++)
        #pragma unroll
        for (int h = 0; h < 2; h++) {
            float s = ssq[mt][h];
            s += __shfl_xor_sync(0xffffffffu, s, 1);
            s += __shfl_xor_sync(0xffffffffu, s, 2);
            if (tg == 0) atomicAdd(&ssm[wm * 64 + mt * 16 + gp + 8 * h], s);
        }
    __syncthreads();
    uint32_t* up = g_ub + (size_t)(e * BB + b) * UROWS * 64;
    #pragma unroll
    for (int mt = 0; mt < 4; mt++)
        #pragma unroll
        for (int h = 0; h < 2; h++) {
            int r = wm * 64 + mt * 16 + gp + 8 * h;
            int q = q0 + r;
            float s = ssm[r];
            float sc = s / (1.f + s) * rsqrtf(s + 1e-8f);
            #pragma unroll
            for (int nt = 0; nt < 4; nt++) {
                up[(size_t)q * 64 + wn * 16 + nt * 4 + tg] =
                    f2h2(acc[mt][nt][h * 2] * sc, acc[mt][nt][h * 2 + 1] * sc);
            }
        }
}

// ---------------- pw: fp16 K-stacked GEMM, M=128, 256 threads (R13 proven) -----------
#define PW_US0 0
#define PW_US1 2560
#define PW_WS0 5120
#define PW_WS1 7680
#define PW_BIAS 16896            // stage[128][132] floats reuses words 0..16895
#define PW_SMEMB ((16896 + 128) * 4)   // 68,096 B

__global__ void __launch_bounds__(256) k_pw_mma(float* __restrict__ out) {
    int g = blockIdx.z, b = blockIdx.y, q0 = blockIdx.x * 128;
    extern __shared__ uint32_t S[];
    float* bias = (float*)(S + PW_BIAS);
    int t = threadIdx.x, lane = t & 31, wid = t >> 5;
    int wm = wid & 3, wn = wid >> 2;
    int gp = lane >> 2, tg = lane & 3;
    uint32_t sbase = smem_u32(S);
    if (t < 128) bias[t] = g_beff[g][b][t];
    float acc[2][8][4];
    #pragma unroll
    for (int mt = 0; mt < 2; mt++)
        #pragma unroll
        for (int nt = 0; nt < 8; nt++)
            #pragma unroll
            for (int k = 0; k < 4; k++) acc[mt][nt][k] = 0.f;

    {   // prologue: chunk0
        int e = g_sel[g][b][0];
        const uint4* usrc = (const uint4*)g_ub + ((size_t)(e * BB + b) * UROWS + q0) * 16;
        for (int i = t; i < 512; i += 256) {
            int r = i >> 2, q = i & 3;
            cpa16(sbase + (PW_US0 + r * 20 + q * 4) * 4, usrc + (size_t)r * 16 + q);
        }
        const uint4* wsrc = (const uint4*)g_bp + (size_t)((g * BB + b) * 2 + 0) * 2048;
        for (int i = t; i < 512; i += 256) {
            int co = i >> 2, q = i & 3;
            cpa16(sbase + (PW_WS0 + co * 20 + q * 4) * 4, wsrc + co * 16 + q);
        }
        cpa_commit();
    }

    for (int kc = 0; kc < 8; kc++) {
        if (kc < 7) {
            int kn = kc + 1, slot = kn >> 2, c = kn & 3;
            int e = g_sel[g][b][slot];
            uint32_t uoff = (kn & 1) ? PW_US1 : PW_US0;
            uint32_t woff = (kn & 1) ? PW_WS1 : PW_WS0;
            const uint4* usrc = (const uint4*)g_ub + ((size_t)(e * BB + b) * UROWS + q0) * 16 + c * 4;
            for (int i = t; i < 512; i += 256) {
                int r = i >> 2, q = i & 3;
                cpa16(sbase + (uoff + r * 20 + q * 4) * 4, usrc + (size_t)r * 16 + q);
            }
            const uint4* wsrc = (const uint4*)g_bp + (size_t)((g * BB + b) * 2 + slot) * 2048 + c * 4;
            for (int i = t; i < 512; i += 256) {
                int co = i >> 2, q = i & 3;
                cpa16(sbase + (woff + co * 20 + q * 4) * 4, wsrc + co * 16 + q);
            }
            cpa_commit();
            cpa_wait1();
        } else {
            cpa_wait0();
        }
        __syncthreads();
        const uint32_t* us = S + ((kc & 1) ? PW_US1 : PW_US0);
        const uint32_t* ws = S + ((kc & 1) ? PW_WS1 : PW_WS0);
        int rb = wm * 32 + gp;
        #pragma unroll
        for (int ks = 0; ks < 2; ks++) {
            int k0 = ks * 8 + tg;
            uint32_t a[2][4];
            #pragma unroll
            for (int mt = 0; mt < 2; mt++) {
                const uint32_t* xp = us + (rb + mt * 16) * 20;
                a[mt][0] = xp[k0];
                a[mt][1] = xp[160 + k0];
                a[mt][2] = xp[k0 + 4];
                a[mt][3] = xp[160 + k0 + 4];
            }
            #pragma unroll
            for (int nt = 0; nt < 8; nt++) {
                int n = wn * 64 + nt * 8 + gp;
                uint32_t b0 = ws[n * 20 + k0];
                uint32_t b1 = ws[n * 20 + k0 + 4];
                mma16(acc[0][nt], a[0], b0, b1);
                mma16(acc[1][nt], a[1], b0, b1);
            }
        }
        __syncthreads();
    }

    // epilogue: transpose through smem -> coalesced global stores
    float* stg = (float*)S;
    #pragma unroll
    for (int mt = 0; mt < 2; mt++)
        #pragma unroll
        for (int k = 0; k < 4; k++) {
            int r = wm * 32 + mt * 16 + gp + 8 * (k >> 1);
            #pragma unroll
            for (int nt = 0; nt < 8; nt++) {
                int col = wn * 64 + nt * 8 + 2 * tg + (k & 1);
                stg[col * 132 + r] = acc[mt][nt][k];
            }
        }
    __syncthreads();
    for (int i = t; i < 16384; i += 256) {
        int co = i >> 7, p = i & 127;
        int q = q0 + p;
        int h = q / 98 - 1, w = q % 98 - 1;
        if ((unsigned)h < 96u && (unsigned)w < 96u)
            out[(((size_t)g * BB + b) * CC + co) * PIX + h * 96 + w] =
                stg[co * 132 + p] + bias[co];
    }
}

// ---------------- launch ----------------
extern "C" void kernel_launch(void* const* d_in, const int* in_sizes, int n_in,
                              void* d_out, int out_size) {
    const float* x  = (const float*)d_in[0];
    const float* G  = (const float*)d_in[1];
    const float* Wc = (const float*)d_in[2];
    const float* bc = (const float*)d_in[3];
    const float* Wp = (const float*)d_in[4];
    const float* bp = (const float*)d_in[5];
    float* out = (float*)d_out;

    cudaFuncSetAttribute(k_conv_mma, cudaFuncAttributeMaxDynamicSharedMemorySize, CV_SMEMB);
    cudaFuncSetAttribute(k_pw_mma,   cudaFuncAttributeMaxDynamicSharedMemorySize, PW_SMEMB);

    k_prep<<<2752, 256>>>(x, Wc);
    k_gate<<<1, 128>>>(G, bp, out);
    k_packbp<<<512, 256>>>(Wp);
    k_conv_mma<<<dim3(NT2, BB, EE), 512, CV_SMEMB>>>(bc);
    k_pw_mma<<<dim3(NTT, BB, NG), 256, PW_SMEMB>>>(out);
}